// round 4
// baseline (speedup 1.0000x reference)
#include <cuda_runtime.h>
#include <cstdint>

// Fixed problem shape: predictions/target are [1024, 8192] fp32.
#define BB 1024
#define NN 8192
#define KK 10
#define THREADS 256
#define NWARP (THREADS / 32)
#define ITERS ((NN / 4) / THREADS)   // 8 float4 iters per thread
#define CAP 416                      // candidate buffer (13 per lane of warp 0)
#define FILT_T 0.99f

typedef unsigned long long u64;

// Static device scratch (no allocations allowed).
__device__ float g_partial[BB];
__device__ unsigned int g_ticket;    // zero-init at load; reset by last block

__device__ __forceinline__ u64 umax64(u64 a, u64 b) { return a > b ? a : b; }

// key = ((fbits+1)<<13) | (NN-1-idx): monotone in value (targets >= 0),
// min-index tie-break, all keys > 0 and globally unique per row.
__device__ __forceinline__ u64 pack_key(float v, int idx) {
    return (((u64)__float_as_uint(v) + 1ull) << 13) | (u64)(NN - 1 - idx);
}

__device__ __forceinline__ u64 pack2(float lo, float hi) {
    u64 r; asm("mov.b64 %0, {%1, %2};" : "=l"(r) : "f"(lo), "f"(hi)); return r;
}
__device__ __forceinline__ u64 add2(u64 a, u64 b) {
    u64 r; asm("add.rn.f32x2 %0, %1, %2;" : "=l"(r) : "l"(a), "l"(b)); return r;
}
__device__ __forceinline__ float sum2(u64 a) {
    float x, y; asm("mov.b64 {%0, %1}, %2;" : "=f"(x), "=f"(y) : "l"(a));
    return x + y;
}

__device__ __forceinline__ unsigned smem_u32(const void* p) {
    unsigned a;
    asm("{ .reg .u64 t; cvta.to.shared.u64 t, %1; cvt.u32.u64 %0, t; }"
        : "=r"(a) : "l"(p));
    return a;
}
__device__ __forceinline__ void cp_async16(unsigned saddr, const void* gptr) {
    asm volatile("cp.async.cg.shared.global [%0], [%1], 16;"
                 :: "r"(saddr), "l"(gptr));
}

__global__ __launch_bounds__(THREADS)
void vml_kernel(const float* __restrict__ pred,
                const float* __restrict__ targ,
                float* __restrict__ out) {
    const int row  = blockIdx.x;
    const int tid  = threadIdx.x;
    const int lane = tid & 31;
    const int warp = tid >> 5;

    const float4* t4 = reinterpret_cast<const float4*>(targ + (size_t)row * NN);
    const float4* p4g = reinterpret_cast<const float4*>(pred + (size_t)row * NN);

    __shared__ float s_pred[NN];              // 32 KB pred row staging
    __shared__ int  s_count;
    __shared__ u64  s_cand[CAP];
    __shared__ u64  s_warp_top[NWARP * KK];   // fallback only
    __shared__ float s_t[KK];
    __shared__ int   s_i[KK];
    __shared__ float s_p[KK];
    __shared__ float s_c[KK];
    __shared__ float s_sums[NWARP][KK];
    __shared__ float s_sumx[NWARP];
    __shared__ float s_loss[KK];
    __shared__ bool  s_last;

    // ---- Kick off async pred-row copy to smem (overlaps all of Phase A) ----
    {
        unsigned sbase = smem_u32(s_pred);
#pragma unroll
        for (int it = 0; it < ITERS; it++) {
            int f4i = tid + it * THREADS;
            cp_async16(sbase + f4i * 16, p4g + f4i);
        }
        asm volatile("cp.async.commit_group;");
    }

    // ---------------- Phase A: top-10 of target via threshold filter ----------
    if (tid == 0) s_count = 0;
    __syncthreads();

#pragma unroll
    for (int it = 0; it < ITERS; it++) {
        const int f4i = tid + it * THREADS;
        float4 t = t4[f4i];
        const int base = f4i * 4;
        float vals[4] = {t.x, t.y, t.z, t.w};
#pragma unroll
        for (int e = 0; e < 4; e++) {
            if (vals[e] > FILT_T) {
                int p = atomicAdd(&s_count, 1);
                if (p < CAP) s_cand[p] = pack_key(vals[e], base + e);
            }
        }
    }
    __syncthreads();

    const bool filter_ok = (s_count >= KK && s_count <= CAP);

    if (filter_ok) {
        // Warp 0: exact top-10 over <=416 unique candidate keys.
        if (warp == 0) {
            const int cnt = s_count;
            u64 loc[CAP / 32];
#pragma unroll
            for (int i = 0; i < CAP / 32; i++) {
                int ix = lane + i * 32;
                loc[i] = (ix < cnt) ? s_cand[ix] : 0ull;
            }
#pragma unroll
            for (int r = 0; r < KK; r++) {
                u64 lm = loc[0];
#pragma unroll
                for (int i = 1; i < CAP / 32; i++) lm = umax64(lm, loc[i]);
                u64 m = lm;
#pragma unroll
                for (int off = 16; off > 0; off >>= 1)
                    m = umax64(m, __shfl_xor_sync(0xffffffffu, m, off));
#pragma unroll
                for (int i = 0; i < CAP / 32; i++)
                    if (loc[i] == m) loc[i] = 0ull;   // unique: one match total
                if (lane == r) {
                    s_t[r] = __uint_as_float((unsigned)(m >> 13) - 1u);
                    s_i[r] = (NN - 1) - (int)(m & (u64)(NN - 1));
                }
            }
        }
    } else {
        // ---------- Exact fallback (verified round-2 path) ----------
        u64 v[KK];
#pragma unroll
        for (int i = 0; i < KK; i++) v[i] = 0ull;
#pragma unroll
        for (int it = 0; it < ITERS; it++) {
            const int f4i = tid + it * THREADS;
            float4 t = t4[f4i];
            const int base = f4i * 4;
            float vals[4] = {t.x, t.y, t.z, t.w};
#pragma unroll
            for (int e = 0; e < 4; e++) {
                u64 key = pack_key(vals[e], base + e);
                if (key > v[KK - 1]) {
                    v[KK - 1] = key;
#pragma unroll
                    for (int i = KK - 1; i > 0; i--) {
                        if (v[i] > v[i - 1]) { u64 tmp = v[i - 1]; v[i - 1] = v[i]; v[i] = tmp; }
                    }
                }
            }
        }
        {
            u64 head = v[0];
#pragma unroll
            for (int r = 0; r < KK; r++) {
                u64 m = head;
#pragma unroll
                for (int off = 16; off > 0; off >>= 1)
                    m = umax64(m, __shfl_xor_sync(0xffffffffu, m, off));
                if (head == m) {
#pragma unroll
                    for (int i = 0; i < KK - 1; i++) v[i] = v[i + 1];
                    v[KK - 1] = 0ull;
                    head = v[0];
                }
                if (lane == 0) s_warp_top[warp * KK + r] = m;
            }
        }
        __syncthreads();
        if (warp == 0) {
            u64 k0 = s_warp_top[lane];
            u64 k1 = s_warp_top[lane + 32];
            u64 k2 = (lane + 64 < NWARP * KK) ? s_warp_top[lane + 64] : 0ull;
#pragma unroll
            for (int r = 0; r < KK; r++) {
                u64 m = umax64(k0, umax64(k1, k2));
#pragma unroll
                for (int off = 16; off > 0; off >>= 1)
                    m = umax64(m, __shfl_xor_sync(0xffffffffu, m, off));
                if (k0 == m) k0 = 0ull;
                else if (k1 == m) k1 = 0ull;
                else if (k2 == m) k2 = 0ull;
                if (lane == r) {
                    s_t[r] = __uint_as_float((unsigned)(m >> 13) - 1u);
                    s_i[r] = (NN - 1) - (int)(m & (u64)(NN - 1));
                }
            }
        }
    }

    // Pred row must be resident in smem from here on.
    asm volatile("cp.async.wait_group 0;");
    __syncthreads();

    // Gather top predictions from smem; c_k = 0.5*t_k - p_k.
    if (tid < KK) {
        float pk = s_pred[s_i[tid]];
        s_p[tid] = pk;
        s_c[tid] = 0.5f * s_t[tid] - pk;
    }
    __syncthreads();

    // ---------------- Phase B: A_k = sum_j |c_k + x_j|, Sx = sum_j x_j -------
    // relu(d) = 0.5*(d + |d|) exactly in fp32; sum_j relu(c_k+x_j)
    //   = 0.5*(NN*c_k + Sx + A_k).
    const u64 ABSMASK = 0x7fffffff7fffffffull;
    u64 c2[KK], a2[KK];
#pragma unroll
    for (int k = 0; k < KK; k++) { float c = s_c[k]; c2[k] = pack2(c, c); a2[k] = 0ull; }
    u64 sx2 = 0ull;

    const float4* p4s = reinterpret_cast<const float4*>(s_pred);
#pragma unroll
    for (int it = 0; it < ITERS; it++) {
        float4 p = p4s[tid + it * THREADS];
        u64 x01 = pack2(p.x, p.y);
        u64 x23 = pack2(p.z, p.w);
        sx2 = add2(sx2, x01);
        sx2 = add2(sx2, x23);
#pragma unroll
        for (int k = 0; k < KK; k++) {
            u64 d0 = add2(c2[k], x01) & ABSMASK;
            a2[k] = add2(a2[k], d0);
            u64 d1 = add2(c2[k], x23) & ABSMASK;
            a2[k] = add2(a2[k], d1);
        }
    }

    float A[KK];
#pragma unroll
    for (int k = 0; k < KK; k++) A[k] = sum2(a2[k]);
    float sx = sum2(sx2);

#pragma unroll
    for (int k = 0; k < KK; k++) {
#pragma unroll
        for (int off = 16; off > 0; off >>= 1)
            A[k] += __shfl_xor_sync(0xffffffffu, A[k], off);
    }
#pragma unroll
    for (int off = 16; off > 0; off >>= 1)
        sx += __shfl_xor_sync(0xffffffffu, sx, off);

    if (lane == 0) {
#pragma unroll
        for (int k = 0; k < KK; k++) s_sums[warp][k] = A[k];
        s_sumx[warp] = sx;
    }
    __syncthreads();

    if (tid < KK) {
        const int k = tid;
        float Ak = 0.f, Sx = 0.f;
#pragma unroll
        for (int w = 0; w < NWARP; w++) { Ak += s_sums[w][k]; Sx += s_sumx[w]; }
        float ck = s_c[k];
        float S_full = 0.5f * (fmaf((float)NN, ck, Sx) + Ak);
        float sub = 0.f;
        for (int r = 0; r <= k; r++) sub += fmaxf(ck + s_p[r], 0.f);
        float per = (S_full - sub) / (float)(NN - k);
        s_loss[k] = (s_t[k] > 0.25f) ? per : 0.f;
    }
    __syncthreads();

    if (tid == 0) {
        float acc = 0.f;
#pragma unroll
        for (int k = 0; k < KK; k++) acc += s_loss[k];
        g_partial[row] = acc;
        __threadfence();
        unsigned t = atomicAdd(&g_ticket, 1u);
        s_last = (t == BB - 1);
    }
    __syncthreads();

    // Last block: deterministic reduction of all 1024 row partials.
    if (s_last) {
        __threadfence();
        float v = g_partial[tid] + g_partial[tid + 256] +
                  g_partial[tid + 512] + g_partial[tid + 768];
        __shared__ float sred[THREADS];
        sred[tid] = v;
        __syncthreads();
#pragma unroll
        for (int stride = THREADS / 2; stride > 0; stride >>= 1) {
            if (tid < stride) sred[tid] += sred[tid + stride];
            __syncthreads();
        }
        if (tid == 0) {
            out[0] = sred[0];
            g_ticket = 0;   // reset for next graph replay
        }
    }
}

extern "C" void kernel_launch(void* const* d_in, const int* in_sizes, int n_in,
                              void* d_out, int out_size) {
    const float* pred = (const float*)d_in[0];
    const float* targ = (const float*)d_in[1];
    vml_kernel<<<BB, THREADS>>>(pred, targ, (float*)d_out);
}

// round 5
// speedup vs baseline: 1.0588x; 1.0588x over previous
#include <cuda_runtime.h>
#include <cstdint>

// Fixed problem shape: predictions/target are [1024, 8192] fp32.
#define BB 1024
#define NN 8192
#define KK 10
#define THREADS 256
#define NWARP (THREADS / 32)
#define ITERS ((NN / 4) / THREADS)   // 8 float4 iters per thread
#define CAP 128                      // candidate buffer (4 per lane of warp 0)
#define FILT_T 0.995f

typedef unsigned long long u64;

// Static device scratch (no allocations allowed).
__device__ float g_partial[BB];
__device__ unsigned int g_ticket;    // zero-init at load; reset by last block

__device__ __forceinline__ u64 umax64(u64 a, u64 b) { return a > b ? a : b; }

// key = ((fbits+1)<<13) | (NN-1-idx): monotone in value (targets >= 0),
// min-index tie-break, all keys > 0 and globally unique per row.
__device__ __forceinline__ u64 pack_key(float v, int idx) {
    return (((u64)__float_as_uint(v) + 1ull) << 13) | (u64)(NN - 1 - idx);
}

__device__ __forceinline__ u64 pack2(float lo, float hi) {
    u64 r; asm("mov.b64 %0, {%1, %2};" : "=l"(r) : "f"(lo), "f"(hi)); return r;
}
__device__ __forceinline__ u64 add2(u64 a, u64 b) {
    u64 r; asm("add.rn.f32x2 %0, %1, %2;" : "=l"(r) : "l"(a), "l"(b)); return r;
}
__device__ __forceinline__ float sum2(u64 a) {
    float x, y; asm("mov.b64 {%0, %1}, %2;" : "=f"(x), "=f"(y) : "l"(a));
    return x + y;
}

__global__ __launch_bounds__(THREADS)
void vml_kernel(const float* __restrict__ pred,
                const float* __restrict__ targ,
                float* __restrict__ out) {
    const int row  = blockIdx.x;
    const int tid  = threadIdx.x;
    const int lane = tid & 31;
    const int warp = tid >> 5;

    const float4* t4 = reinterpret_cast<const float4*>(targ + (size_t)row * NN);
    const float4* p4 = reinterpret_cast<const float4*>(pred + (size_t)row * NN);
    const float* pred_row = pred + (size_t)row * NN;

    __shared__ int  s_count;
    __shared__ u64  s_cand[CAP];
    __shared__ u64  s_warp_top[NWARP * KK];   // fallback only
    __shared__ float s_t[KK];
    __shared__ int   s_i[KK];
    __shared__ float s_p[KK];
    __shared__ float s_c[KK];
    __shared__ float s_sums[NWARP][KK];
    __shared__ float s_sumx[NWARP];
    __shared__ float s_loss[KK];
    __shared__ bool  s_last;

    // Warm L2 with the pred row while Phase A runs (no smem/reg cost).
#pragma unroll
    for (int it = 0; it < ITERS; it++) {
        asm volatile("prefetch.global.L2 [%0];" :: "l"(p4 + tid + it * THREADS));
    }

    // ---------------- Phase A: top-10 of target via threshold filter ----------
    if (tid == 0) s_count = 0;
    __syncthreads();

#pragma unroll
    for (int it = 0; it < ITERS; it++) {
        const int f4i = tid + it * THREADS;
        float4 t = t4[f4i];
        // Vector fast-reject: only ~2% of float4s contain a candidate.
        float vmax = fmaxf(fmaxf(t.x, t.y), fmaxf(t.z, t.w));
        if (vmax > FILT_T) {
            const int base = f4i * 4;
            float vals[4] = {t.x, t.y, t.z, t.w};
#pragma unroll
            for (int e = 0; e < 4; e++) {
                if (vals[e] > FILT_T) {
                    int p = atomicAdd(&s_count, 1);
                    if (p < CAP) s_cand[p] = pack_key(vals[e], base + e);
                }
            }
        }
    }
    __syncthreads();

    const bool filter_ok = (s_count >= KK && s_count <= CAP);

    if (filter_ok) {
        // Warp 0: exact top-10 over <=128 unique candidate keys.
        if (warp == 0) {
            const int cnt = s_count;
            u64 loc[CAP / 32];
#pragma unroll
            for (int i = 0; i < CAP / 32; i++) {
                int ix = lane + i * 32;
                loc[i] = (ix < cnt) ? s_cand[ix] : 0ull;
            }
#pragma unroll
            for (int r = 0; r < KK; r++) {
                u64 lm = loc[0];
#pragma unroll
                for (int i = 1; i < CAP / 32; i++) lm = umax64(lm, loc[i]);
                u64 m = lm;
#pragma unroll
                for (int off = 16; off > 0; off >>= 1)
                    m = umax64(m, __shfl_xor_sync(0xffffffffu, m, off));
#pragma unroll
                for (int i = 0; i < CAP / 32; i++)
                    if (loc[i] == m) loc[i] = 0ull;   // unique: one match total
                if (lane == r) {
                    s_t[r] = __uint_as_float((unsigned)(m >> 13) - 1u);
                    s_i[r] = (NN - 1) - (int)(m & (u64)(NN - 1));
                }
            }
        }
    } else {
        // ---------- Exact fallback (verified round-2 path) ----------
        u64 v[KK];
#pragma unroll
        for (int i = 0; i < KK; i++) v[i] = 0ull;
#pragma unroll
        for (int it = 0; it < ITERS; it++) {
            const int f4i = tid + it * THREADS;
            float4 t = t4[f4i];
            const int base = f4i * 4;
            float vals[4] = {t.x, t.y, t.z, t.w};
#pragma unroll
            for (int e = 0; e < 4; e++) {
                u64 key = pack_key(vals[e], base + e);
                if (key > v[KK - 1]) {
                    v[KK - 1] = key;
#pragma unroll
                    for (int i = KK - 1; i > 0; i--) {
                        if (v[i] > v[i - 1]) { u64 tmp = v[i - 1]; v[i - 1] = v[i]; v[i] = tmp; }
                    }
                }
            }
        }
        {
            u64 head = v[0];
#pragma unroll
            for (int r = 0; r < KK; r++) {
                u64 m = head;
#pragma unroll
                for (int off = 16; off > 0; off >>= 1)
                    m = umax64(m, __shfl_xor_sync(0xffffffffu, m, off));
                if (head == m) {
#pragma unroll
                    for (int i = 0; i < KK - 1; i++) v[i] = v[i + 1];
                    v[KK - 1] = 0ull;
                    head = v[0];
                }
                if (lane == 0) s_warp_top[warp * KK + r] = m;
            }
        }
        __syncthreads();
        if (warp == 0) {
            u64 k0 = s_warp_top[lane];
            u64 k1 = s_warp_top[lane + 32];
            u64 k2 = (lane + 64 < NWARP * KK) ? s_warp_top[lane + 64] : 0ull;
#pragma unroll
            for (int r = 0; r < KK; r++) {
                u64 m = umax64(k0, umax64(k1, k2));
#pragma unroll
                for (int off = 16; off > 0; off >>= 1)
                    m = umax64(m, __shfl_xor_sync(0xffffffffu, m, off));
                if (k0 == m) k0 = 0ull;
                else if (k1 == m) k1 = 0ull;
                else if (k2 == m) k2 = 0ull;
                if (lane == r) {
                    s_t[r] = __uint_as_float((unsigned)(m >> 13) - 1u);
                    s_i[r] = (NN - 1) - (int)(m & (u64)(NN - 1));
                }
            }
        }
    }
    __syncthreads();

    // Gather top predictions; c_k = 0.5*t_k - p_k.
    if (tid < KK) {
        float pk = pred_row[s_i[tid]];
        s_p[tid] = pk;
        s_c[tid] = 0.5f * s_t[tid] - pk;
    }
    __syncthreads();

    // ---------------- Phase B: A_k = sum_j |c_k + x_j|, Sx = sum_j x_j -------
    // relu(d) = 0.5*(d + |d|) exactly in fp32; sum_j relu(c_k+x_j)
    //   = 0.5*(NN*c_k + Sx + A_k).
    const u64 ABSMASK = 0x7fffffff7fffffffull;
    u64 c2[KK], a2[KK];
#pragma unroll
    for (int k = 0; k < KK; k++) { float c = s_c[k]; c2[k] = pack2(c, c); a2[k] = 0ull; }
    u64 sx2 = 0ull;

#pragma unroll
    for (int it = 0; it < ITERS; it++) {
        float4 p = p4[tid + it * THREADS];
        u64 x01 = pack2(p.x, p.y);
        u64 x23 = pack2(p.z, p.w);
        sx2 = add2(sx2, x01);
        sx2 = add2(sx2, x23);
#pragma unroll
        for (int k = 0; k < KK; k++) {
            u64 d0 = add2(c2[k], x01) & ABSMASK;
            a2[k] = add2(a2[k], d0);
            u64 d1 = add2(c2[k], x23) & ABSMASK;
            a2[k] = add2(a2[k], d1);
        }
    }

    float A[KK];
#pragma unroll
    for (int k = 0; k < KK; k++) A[k] = sum2(a2[k]);
    float sx = sum2(sx2);

#pragma unroll
    for (int k = 0; k < KK; k++) {
#pragma unroll
        for (int off = 16; off > 0; off >>= 1)
            A[k] += __shfl_xor_sync(0xffffffffu, A[k], off);
    }
#pragma unroll
    for (int off = 16; off > 0; off >>= 1)
        sx += __shfl_xor_sync(0xffffffffu, sx, off);

    if (lane == 0) {
#pragma unroll
        for (int k = 0; k < KK; k++) s_sums[warp][k] = A[k];
        s_sumx[warp] = sx;
    }
    __syncthreads();

    if (tid < KK) {
        const int k = tid;
        float Ak = 0.f, Sx = 0.f;
#pragma unroll
        for (int w = 0; w < NWARP; w++) { Ak += s_sums[w][k]; Sx += s_sumx[w]; }
        float ck = s_c[k];
        float S_full = 0.5f * (fmaf((float)NN, ck, Sx) + Ak);
        float sub = 0.f;
        for (int r = 0; r <= k; r++) sub += fmaxf(ck + s_p[r], 0.f);
        float per = (S_full - sub) / (float)(NN - k);
        s_loss[k] = (s_t[k] > 0.25f) ? per : 0.f;
    }
    __syncthreads();

    if (tid == 0) {
        float acc = 0.f;
#pragma unroll
        for (int k = 0; k < KK; k++) acc += s_loss[k];
        g_partial[row] = acc;
        __threadfence();
        unsigned t = atomicAdd(&g_ticket, 1u);
        s_last = (t == BB - 1);
    }
    __syncthreads();

    // Last block: deterministic reduction of all 1024 row partials.
    if (s_last) {
        __threadfence();
        float v = g_partial[tid] + g_partial[tid + 256] +
                  g_partial[tid + 512] + g_partial[tid + 768];
        __shared__ float sred[THREADS];
        sred[tid] = v;
        __syncthreads();
#pragma unroll
        for (int stride = THREADS / 2; stride > 0; stride >>= 1) {
            if (tid < stride) sred[tid] += sred[tid + stride];
            __syncthreads();
        }
        if (tid == 0) {
            out[0] = sred[0];
            g_ticket = 0;   // reset for next graph replay
        }
    }
}

extern "C" void kernel_launch(void* const* d_in, const int* in_sizes, int n_in,
                              void* d_out, int out_size) {
    const float* pred = (const float*)d_in[0];
    const float* targ = (const float*)d_in[1];
    vml_kernel<<<BB, THREADS>>>(pred, targ, (float*)d_out);
}

// round 7
// speedup vs baseline: 1.1698x; 1.1048x over previous
#include <cuda_runtime.h>
#include <cstdint>

// Fixed problem shape: predictions/target are [1024, 8192] fp32.
#define BB 1024
#define NN 8192
#define KK 10
#define THREADS 128
#define NWARP (THREADS / 32)         // 4
#define ITERS ((NN / 4) / THREADS)   // 16 float4 iters per thread
#define CAP 128                      // candidate buffer (4 per lane of warp 0)
#define FILT_T 0.995f

typedef unsigned long long u64;

// Static device scratch (no allocations allowed).
__device__ float g_partial[BB];
__device__ unsigned int g_ticket;    // zero-init at load; reset by last block

__device__ __forceinline__ u64 umax64(u64 a, u64 b) { return a > b ? a : b; }

// key = ((fbits+1)<<13) | (NN-1-idx): monotone in value (targets >= 0),
// min-index tie-break, all keys > 0 and globally unique per row.
__device__ __forceinline__ u64 pack_key(float v, int idx) {
    return (((u64)__float_as_uint(v) + 1ull) << 13) | (u64)(NN - 1 - idx);
}

__device__ __forceinline__ u64 pack2(float lo, float hi) {
    u64 r; asm("mov.b64 %0, {%1, %2};" : "=l"(r) : "f"(lo), "f"(hi)); return r;
}
__device__ __forceinline__ u64 add2(u64 a, u64 b) {
    u64 r; asm("add.rn.f32x2 %0, %1, %2;" : "=l"(r) : "l"(a), "l"(b)); return r;
}
__device__ __forceinline__ float sum2(u64 a) {
    float x, y; asm("mov.b64 {%0, %1}, %2;" : "=f"(x), "=f"(y) : "l"(a));
    return x + y;
}

__global__ __launch_bounds__(THREADS, 8)
void vml_kernel(const float* __restrict__ pred,
                const float* __restrict__ targ,
                float* __restrict__ out) {
    const int row  = blockIdx.x;
    const int tid  = threadIdx.x;
    const int lane = tid & 31;
    const int warp = tid >> 5;

    const float4* t4 = reinterpret_cast<const float4*>(targ + (size_t)row * NN);
    const float4* p4 = reinterpret_cast<const float4*>(pred + (size_t)row * NN);
    const float* pred_row = pred + (size_t)row * NN;

    __shared__ int  s_count;
    __shared__ u64  s_cand[CAP];
    __shared__ u64  s_warp_top[NWARP * KK];   // fallback only (40 keys)
    __shared__ float s_t[KK];
    __shared__ int   s_i[KK];
    __shared__ float s_p[KK];
    __shared__ float s_c[KK];
    __shared__ float s_sums[NWARP][KK];
    __shared__ float s_sumx[NWARP];
    __shared__ float s_loss[KK];
    __shared__ bool  s_last;

    // Warm L2 with the pred row while Phase A runs (no smem/reg cost).
#pragma unroll
    for (int it = 0; it < ITERS; it++) {
        asm volatile("prefetch.global.L2 [%0];" :: "l"(p4 + tid + it * THREADS));
    }

    // ---------------- Phase A: top-10 of target via threshold filter ----------
    if (tid == 0) s_count = 0;
    __syncthreads();

#pragma unroll
    for (int it = 0; it < ITERS; it++) {
        const int f4i = tid + it * THREADS;
        float4 t = t4[f4i];
        // Vector fast-reject: only ~2% of float4s contain a candidate.
        float vmax = fmaxf(fmaxf(t.x, t.y), fmaxf(t.z, t.w));
        if (vmax > FILT_T) {
            const int base = f4i * 4;
            float vals[4] = {t.x, t.y, t.z, t.w};
#pragma unroll
            for (int e = 0; e < 4; e++) {
                if (vals[e] > FILT_T) {
                    int p = atomicAdd(&s_count, 1);
                    if (p < CAP) s_cand[p] = pack_key(vals[e], base + e);
                }
            }
        }
    }
    __syncthreads();

    const bool filter_ok = (s_count >= KK && s_count <= CAP);

    if (filter_ok) {
        // Warp 0: exact top-10 over <=128 unique candidate keys.
        if (warp == 0) {
            const int cnt = s_count;
            u64 loc[CAP / 32];
#pragma unroll
            for (int i = 0; i < CAP / 32; i++) {
                int ix = lane + i * 32;
                loc[i] = (ix < cnt) ? s_cand[ix] : 0ull;
            }
#pragma unroll
            for (int r = 0; r < KK; r++) {
                u64 lm = loc[0];
#pragma unroll
                for (int i = 1; i < CAP / 32; i++) lm = umax64(lm, loc[i]);
                u64 m = lm;
#pragma unroll
                for (int off = 16; off > 0; off >>= 1)
                    m = umax64(m, __shfl_xor_sync(0xffffffffu, m, off));
#pragma unroll
                for (int i = 0; i < CAP / 32; i++)
                    if (loc[i] == m) loc[i] = 0ull;   // unique: one match total
                if (lane == r) {
                    s_t[r] = __uint_as_float((unsigned)(m >> 13) - 1u);
                    s_i[r] = (NN - 1) - (int)(m & (u64)(NN - 1));
                }
            }
        }
    } else {
        // ---------- Exact fallback (verified round-2 path) ----------
        u64 v[KK];
#pragma unroll
        for (int i = 0; i < KK; i++) v[i] = 0ull;
#pragma unroll
        for (int it = 0; it < ITERS; it++) {
            const int f4i = tid + it * THREADS;
            float4 t = t4[f4i];
            const int base = f4i * 4;
            float vals[4] = {t.x, t.y, t.z, t.w};
#pragma unroll
            for (int e = 0; e < 4; e++) {
                u64 key = pack_key(vals[e], base + e);
                if (key > v[KK - 1]) {
                    v[KK - 1] = key;
#pragma unroll
                    for (int i = KK - 1; i > 0; i--) {
                        if (v[i] > v[i - 1]) { u64 tmp = v[i - 1]; v[i - 1] = v[i]; v[i] = tmp; }
                    }
                }
            }
        }
        {
            u64 head = v[0];
#pragma unroll
            for (int r = 0; r < KK; r++) {
                u64 m = head;
#pragma unroll
                for (int off = 16; off > 0; off >>= 1)
                    m = umax64(m, __shfl_xor_sync(0xffffffffu, m, off));
                if (head == m) {
#pragma unroll
                    for (int i = 0; i < KK - 1; i++) v[i] = v[i + 1];
                    v[KK - 1] = 0ull;
                    head = v[0];
                }
                if (lane == 0) s_warp_top[warp * KK + r] = m;
            }
        }
        __syncthreads();
        if (warp == 0) {
            // 40 candidate keys across 2 strided slots.
            u64 k0 = s_warp_top[lane];
            u64 k1 = (lane + 32 < NWARP * KK) ? s_warp_top[lane + 32] : 0ull;
#pragma unroll
            for (int r = 0; r < KK; r++) {
                u64 m = umax64(k0, k1);
#pragma unroll
                for (int off = 16; off > 0; off >>= 1)
                    m = umax64(m, __shfl_xor_sync(0xffffffffu, m, off));
                if (k0 == m) k0 = 0ull;
                else if (k1 == m) k1 = 0ull;
                if (lane == r) {
                    s_t[r] = __uint_as_float((unsigned)(m >> 13) - 1u);
                    s_i[r] = (NN - 1) - (int)(m & (u64)(NN - 1));
                }
            }
        }
    }
    __syncthreads();

    // Gather top predictions; c_k = 0.5*t_k - p_k.
    if (tid < KK) {
        float pk = pred_row[s_i[tid]];
        s_p[tid] = pk;
        s_c[tid] = 0.5f * s_t[tid] - pk;
    }
    __syncthreads();

    // ---------------- Phase B: A_k = sum_j |c_k + x_j|, Sx = sum_j x_j -------
    // relu(d) = 0.5*(d + |d|) exactly in fp32; sum_j relu(c_k+x_j)
    //   = 0.5*(NN*c_k + Sx + A_k).
    const u64 ABSMASK = 0x7fffffff7fffffffull;
    u64 c2[KK], a2[KK];
#pragma unroll
    for (int k = 0; k < KK; k++) { float c = s_c[k]; c2[k] = pack2(c, c); a2[k] = 0ull; }
    u64 sx2 = 0ull;

#pragma unroll
    for (int it = 0; it < ITERS; it++) {
        float4 p = p4[tid + it * THREADS];
        u64 x01 = pack2(p.x, p.y);
        u64 x23 = pack2(p.z, p.w);
        sx2 = add2(sx2, x01);
        sx2 = add2(sx2, x23);
#pragma unroll
        for (int k = 0; k < KK; k++) {
            u64 d0 = add2(c2[k], x01) & ABSMASK;
            a2[k] = add2(a2[k], d0);
            u64 d1 = add2(c2[k], x23) & ABSMASK;
            a2[k] = add2(a2[k], d1);
        }
    }

    float A[KK];
#pragma unroll
    for (int k = 0; k < KK; k++) A[k] = sum2(a2[k]);
    float sx = sum2(sx2);

#pragma unroll
    for (int k = 0; k < KK; k++) {
#pragma unroll
        for (int off = 16; off > 0; off >>= 1)
            A[k] += __shfl_xor_sync(0xffffffffu, A[k], off);
    }
#pragma unroll
    for (int off = 16; off > 0; off >>= 1)
        sx += __shfl_xor_sync(0xffffffffu, sx, off);

    if (lane == 0) {
#pragma unroll
        for (int k = 0; k < KK; k++) s_sums[warp][k] = A[k];
        s_sumx[warp] = sx;
    }
    __syncthreads();

    if (tid < KK) {
        const int k = tid;
        float Ak = 0.f, Sx = 0.f;
#pragma unroll
        for (int w = 0; w < NWARP; w++) { Ak += s_sums[w][k]; Sx += s_sumx[w]; }
        float ck = s_c[k];
        float S_full = 0.5f * (fmaf((float)NN, ck, Sx) + Ak);
        float sub = 0.f;
        for (int r = 0; r <= k; r++) sub += fmaxf(ck + s_p[r], 0.f);
        float per = (S_full - sub) / (float)(NN - k);
        s_loss[k] = (s_t[k] > 0.25f) ? per : 0.f;
    }
    __syncthreads();

    if (tid == 0) {
        float acc = 0.f;
#pragma unroll
        for (int k = 0; k < KK; k++) acc += s_loss[k];
        g_partial[row] = acc;
        __threadfence();
        unsigned t = atomicAdd(&g_ticket, 1u);
        s_last = (t == BB - 1);
    }
    __syncthreads();

    // Last block: deterministic reduction of all 1024 row partials.
    if (s_last) {
        __threadfence();
        float v = 0.f;
#pragma unroll
        for (int j = 0; j < BB / THREADS; j++)
            v += g_partial[tid + j * THREADS];
        __shared__ float sred[THREADS];
        sred[tid] = v;
        __syncthreads();
#pragma unroll
        for (int stride = THREADS / 2; stride > 0; stride >>= 1) {
            if (tid < stride) sred[tid] += sred[tid + stride];
            __syncthreads();
        }
        if (tid == 0) {
            out[0] = sred[0];
            g_ticket = 0;   // reset for next graph replay
        }
    }
}

extern "C" void kernel_launch(void* const* d_in, const int* in_sizes, int n_in,
                              void* d_out, int out_size) {
    const float* pred = (const float*)d_in[0];
    const float* targ = (const float*)d_in[1];
    vml_kernel<<<BB, THREADS>>>(pred, targ, (float*)d_out);
}